// round 2
// baseline (speedup 1.0000x reference)
#include <cuda_runtime.h>

#define B_ 8
#define C_ 256
#define N_ 4096
#define ELEMS (B_ * C_ * N_)

// Scratch (device globals; no allocation anywhere)
__device__ float g_h[ELEMS];  // [B,C,N] normalized activations
__device__ float g_q[ELEMS];  // [B,C,N]
__device__ float g_k[ELEMS];  // [B,C,N]
__device__ float g_v[ELEMS];  // [B,N,C]
__device__ float g_z[ELEMS];  // [B,C,N] attention output

// ---------------------------------------------------------------------------
// GroupNorm: 32 groups of 8 channels. One block per (batch, group).
// ---------------------------------------------------------------------------
__global__ __launch_bounds__(256) void gn_kernel(const float* __restrict__ x,
                                                 const float* __restrict__ sc,
                                                 const float* __restrict__ bi,
                                                 float* __restrict__ h) {
    int b = blockIdx.x >> 5, g = blockIdx.x & 31;
    int tid = threadIdx.x;
    size_t base = ((size_t)b * C_ + (size_t)g * 8) * N_;
    const float4* x4 = (const float4*)(x + base);
    float4* h4 = (float4*)(h + base);

    float s = 0.f, ss = 0.f;
    for (int i = tid; i < 8192; i += 256) {  // 8 ch * 4096 floats / 4
        float4 v = x4[i];
        s  += v.x + v.y + v.z + v.w;
        ss += v.x * v.x + v.y * v.y + v.z * v.z + v.w * v.w;
    }
    __shared__ float red[512];
    red[tid] = s; red[256 + tid] = ss;
    __syncthreads();
    for (int st = 128; st > 0; st >>= 1) {
        if (tid < st) { red[tid] += red[tid + st]; red[256 + tid] += red[256 + tid + st]; }
        __syncthreads();
    }
    float mean = red[0] * (1.f / 32768.f);
    float var  = red[256] * (1.f / 32768.f) - mean * mean;
    float inv  = rsqrtf(var + 1e-6f);

    for (int i = tid; i < 8192; i += 256) {
        int c = g * 8 + (i >> 10);  // 1024 float4 per channel
        float a  = sc[c] * inv;
        float bb = bi[c] - mean * a;
        float4 v = x4[i];
        h4[i] = make_float4(v.x * a + bb, v.y * a + bb, v.z * a + bb, v.w * a + bb);
    }
}

// ---------------------------------------------------------------------------
// 1x1 conv GEMM: out = W(256x256) @ A[b] (+bias) (+skip)
//   A in [B,C,N]. OUT_NC=false -> out [B,C,N]; OUT_NC=true -> out [B,N,C].
// 64x64 tile, 256 threads, 4x4 register blocking, 16-wide K panels.
// ---------------------------------------------------------------------------
template <bool OUT_NC>
__global__ __launch_bounds__(256) void gemm_kernel(const float* __restrict__ A,
                                                   const float* __restrict__ W,
                                                   const float* __restrict__ bias,
                                                   const float* __restrict__ skip,
                                                   float* __restrict__ out) {
    __shared__ float hs[16][64];  // [ci][n]
    __shared__ float ws[16][64];  // [ci][co]
    int b = blockIdx.z;
    int n0 = blockIdx.x * 64, co0 = blockIdx.y * 64;
    int tid = threadIdx.x, tx = tid & 15, ty = tid >> 4;
    const float* Ab = A + (size_t)b * C_ * N_;
    float acc[4][4] = {};

    for (int k0 = 0; k0 < C_; k0 += 16) {
        *(float4*)&hs[ty][tx * 4] =
            *(const float4*)(Ab + (size_t)(k0 + ty) * N_ + n0 + tx * 4);
#pragma unroll
        for (int u = 0; u < 4; u++)
            ws[ty][tx * 4 + u] = W[(size_t)(co0 + tx * 4 + u) * C_ + k0 + ty];
        __syncthreads();
#pragma unroll
        for (int kk = 0; kk < 16; kk++) {
            float4 r4 = OUT_NC ? *(float4*)&hs[kk][ty * 4] : *(float4*)&ws[kk][ty * 4];
            float4 c4 = OUT_NC ? *(float4*)&ws[kk][tx * 4] : *(float4*)&hs[kk][tx * 4];
            float rv[4] = {r4.x, r4.y, r4.z, r4.w};
            float cv[4] = {c4.x, c4.y, c4.z, c4.w};
#pragma unroll
            for (int a = 0; a < 4; a++)
#pragma unroll
                for (int c = 0; c < 4; c++) acc[a][c] += rv[a] * cv[c];
        }
        __syncthreads();
    }

    if (!OUT_NC) {
#pragma unroll
        for (int a = 0; a < 4; a++) {
            int co = co0 + ty * 4 + a;
            float bb = bias[co];
            size_t off = ((size_t)b * C_ + co) * N_ + n0 + tx * 4;
            float4 r = make_float4(acc[a][0] + bb, acc[a][1] + bb,
                                   acc[a][2] + bb, acc[a][3] + bb);
            if (skip) {
                float4 s4 = *(const float4*)(skip + off);
                r.x += s4.x; r.y += s4.y; r.z += s4.z; r.w += s4.w;
            }
            *(float4*)(out + off) = r;
        }
    } else {
        float4 b4 = *(const float4*)(bias + co0 + tx * 4);
#pragma unroll
        for (int a = 0; a < 4; a++) {
            int n = n0 + ty * 4 + a;
            size_t off = ((size_t)b * N_ + n) * C_ + co0 + tx * 4;
            *(float4*)(out + off) = make_float4(acc[a][0] + b4.x, acc[a][1] + b4.y,
                                                acc[a][2] + b4.z, acc[a][3] + b4.w);
        }
    }
}

// ---------------------------------------------------------------------------
// Flash attention, fp32. One block per (batch, 64-query tile), 256 threads.
//   q,k: [B,C,N]; v: [B,N,C]; z out: [B,C,N].
// smem: Qs[c][i] 64KB, KV (K as [c][j] / V as [j][c]) 64KB, Ps[j][i] 16KB.
// Barrier structure guarantees: KV is read as K-layout only between sync#1
// and sync#2 of an iteration; the V-layout overwrite happens after sync#2;
// V-layout reads happen between sync#3 and the trailing sync. No overlap.
// ---------------------------------------------------------------------------
#define ATTN_SMEM_FLOATS (256 * 64 + 64 * 256 + 64 * 64 + 64 + 64)
#define ATTN_SMEM_BYTES (ATTN_SMEM_FLOATS * 4)

__global__ __launch_bounds__(256, 1) void attn_kernel(const float* __restrict__ q,
                                                      const float* __restrict__ k,
                                                      const float* __restrict__ v,
                                                      float* __restrict__ z) {
    extern __shared__ float sm[];
    float* Qs = sm;                       // [256][64]  Qs[c*64+i]
    float* KV = sm + 256 * 64;            // K: [c*64+j] ; V: [j*256+c]
    float* Ps = KV + 64 * 256;            // [64][64]   Ps[j*64+i]
    float* alpha_s = Ps + 64 * 64;        // [64]
    float* ls = alpha_s + 64;             // [64]

    int b = blockIdx.y;
    int q0 = blockIdx.x * 64;
    int tid = threadIdx.x;
    int ti = tid & 15, tg = tid >> 4;
    const float* qb = q + (size_t)b * C_ * N_;
    const float* kb = k + (size_t)b * C_ * N_;
    const float* vb = v + (size_t)b * N_ * C_;

    // Load Q tile: Qs[c][i]
    {
        int i4 = tid & 15, cb = tid >> 4;
#pragma unroll
        for (int it = 0; it < 16; it++) {
            int c = cb + it * 16;
            *(float4*)&Qs[c * 64 + i4 * 4] =
                *(const float4*)(qb + (size_t)c * N_ + q0 + i4 * 4);
        }
    }

    float m_run = -1e30f, l_run = 0.f;  // live only in threads 0..63
    float o[4][16];
#pragma unroll
    for (int a = 0; a < 4; a++)
#pragma unroll
        for (int c = 0; c < 16; c++) o[a][c] = 0.f;

    for (int j0 = 0; j0 < N_; j0 += 64) {
        // Load K tile: KV[c][j]
        {
            int j4 = tid & 15, cb = tid >> 4;
#pragma unroll
            for (int it = 0; it < 16; it++) {
                int c = cb + it * 16;
                *(float4*)&KV[c * 64 + j4 * 4] =
                    *(const float4*)(kb + (size_t)c * N_ + j0 + j4 * 4);
            }
        }
        __syncthreads();  // sync#1: K tile (and first-iter Q) visible

        // S = Q^T K * scale ; thread (ti,tg): queries ti*4.., keys tg*4..
        float s[4][4] = {};
#pragma unroll 8
        for (int c = 0; c < 256; c++) {
            float4 q4 = *(const float4*)&Qs[c * 64 + ti * 4];
            float4 k4 = *(const float4*)&KV[c * 64 + tg * 4];
            float qa[4] = {q4.x, q4.y, q4.z, q4.w};
            float ka[4] = {k4.x, k4.y, k4.z, k4.w};
#pragma unroll
            for (int a = 0; a < 4; a++)
#pragma unroll
                for (int e = 0; e < 4; e++) s[a][e] += qa[a] * ka[e];
        }
        const float scale = 0.0625f;  // 1/sqrt(256)
#pragma unroll
        for (int e = 0; e < 4; e++)
#pragma unroll
            for (int a = 0; a < 4; a++)
                Ps[(tg * 4 + e) * 64 + ti * 4 + a] = s[a][e] * scale;
        __syncthreads();  // sync#2: Ps ready; all K-layout reads done

        // Online softmax: one thread per query row (threads 0..63)
        if (tid < 64) {
            int i = tid;
            float m = m_run;
#pragma unroll 8
            for (int j = 0; j < 64; j++) m = fmaxf(m, Ps[j * 64 + i]);
            float al = __expf(m_run - m);
            float sum = 0.f;
#pragma unroll 8
            for (int j = 0; j < 64; j++) {
                float p = __expf(Ps[j * 64 + i] - m);
                Ps[j * 64 + i] = p;
                sum += p;
            }
            l_run = l_run * al + sum;
            m_run = m;
            alpha_s[i] = al;
        }
        // Load V tile (overlaps with the softmax work in threads 0..63):
        // KV[j][c] = v[b][j0+j][c]
        {
            int c4 = tid & 63, jb = tid >> 6;
#pragma unroll
            for (int it = 0; it < 16; it++) {
                int j = it * 4 + jb;
                *(float4*)&KV[j * 256 + c4 * 4] =
                    *(const float4*)(vb + (size_t)(j0 + j) * C_ + c4 * 4);
            }
        }
        __syncthreads();  // sync#3: P, alpha, V all ready

        // Rescale accumulators, then O += P * V
        // thread (ti,tg): queries ti*4.., channels tg*16..
        float al4[4];
#pragma unroll
        for (int a = 0; a < 4; a++) al4[a] = alpha_s[ti * 4 + a];
#pragma unroll
        for (int a = 0; a < 4; a++)
#pragma unroll
            for (int c = 0; c < 16; c++) o[a][c] *= al4[a];

#pragma unroll 2
        for (int j = 0; j < 64; j++) {
            float4 p4 = *(const float4*)&Ps[j * 64 + ti * 4];
            float pa[4] = {p4.x, p4.y, p4.z, p4.w};
#pragma unroll
            for (int cq = 0; cq < 4; cq++) {
                float4 v4 = *(const float4*)&KV[j * 256 + tg * 16 + cq * 4];
                float va[4] = {v4.x, v4.y, v4.z, v4.w};
#pragma unroll
                for (int a = 0; a < 4; a++)
#pragma unroll
                    for (int w = 0; w < 4; w++)
                        o[a][cq * 4 + w] += pa[a] * va[w];
            }
        }
        __syncthreads();  // trailing: done reading Ps/KV before next overwrite
    }

    if (tid < 64) ls[tid] = l_run;
    __syncthreads();
    float linv[4];
#pragma unroll
    for (int a = 0; a < 4; a++) linv[a] = 1.f / ls[ti * 4 + a];

    float* zb = z + (size_t)b * C_ * N_;
#pragma unroll
    for (int cc = 0; cc < 16; cc++) {
        int c = tg * 16 + cc;
        float4 r = make_float4(o[0][cc] * linv[0], o[1][cc] * linv[1],
                               o[2][cc] * linv[2], o[3][cc] * linv[3]);
        *(float4*)(zb + (size_t)c * N_ + q0 + ti * 4) = r;
    }
}

// ---------------------------------------------------------------------------
extern "C" void kernel_launch(void* const* d_in, const int* in_sizes, int n_in,
                              void* d_out, int out_size) {
    const float* x  = (const float*)d_in[0];
    const float* gs = (const float*)d_in[1];
    const float* gb = (const float*)d_in[2];
    const float* wq = (const float*)d_in[3];
    const float* bq = (const float*)d_in[4];
    const float* wk = (const float*)d_in[5];
    const float* bk = (const float*)d_in[6];
    const float* wv = (const float*)d_in[7];
    const float* bv = (const float*)d_in[8];
    const float* wo = (const float*)d_in[9];
    const float* bo = (const float*)d_in[10];
    float* out = (float*)d_out;

    float *h, *qp, *kp, *vp, *zp;
    cudaGetSymbolAddress((void**)&h,  g_h);
    cudaGetSymbolAddress((void**)&qp, g_q);
    cudaGetSymbolAddress((void**)&kp, g_k);
    cudaGetSymbolAddress((void**)&vp, g_v);
    cudaGetSymbolAddress((void**)&zp, g_z);

    cudaFuncSetAttribute(attn_kernel, cudaFuncAttributeMaxDynamicSharedMemorySize,
                         ATTN_SMEM_BYTES);

    gn_kernel<<<B_ * 32, 256>>>(x, gs, gb, h);

    dim3 gg(N_ / 64, C_ / 64, B_);
    gemm_kernel<false><<<gg, 256>>>(h, wq, bq, nullptr, qp);  // q: [B,C,N]
    gemm_kernel<false><<<gg, 256>>>(h, wk, bk, nullptr, kp);  // k: [B,C,N]
    gemm_kernel<true ><<<gg, 256>>>(h, wv, bv, nullptr, vp);  // v: [B,N,C]

    attn_kernel<<<dim3(N_ / 64, B_), 256, ATTN_SMEM_BYTES>>>(qp, kp, vp, zp);

    gemm_kernel<false><<<gg, 256>>>(zp, wo, bo, x, out);      // + skip
}

// round 4
// speedup vs baseline: 4.2841x; 4.2841x over previous
#include <cuda_runtime.h>
#include <cuda_fp16.h>
#include <cstdint>

#define B_ 8
#define C_ 256
#define N_ 4096
#define ELEMS (B_ * C_ * N_)

// Scratch (device globals; no allocation anywhere)
__device__ float  g_h[ELEMS];   // [B,C,N] normalized activations (fp32)
__device__ __half g_qt[ELEMS];  // [B,N,C] token-major fp16 (pre-scaled by log2e/16)
__device__ __half g_kt[ELEMS];  // [B,N,C] token-major fp16
__device__ __half g_vc[ELEMS];  // [B,C,N] channel-major fp16
__device__ float  g_z[ELEMS];   // [B,C,N] attention output (fp32)

// ---------------------------------------------------------------------------
// mma.sync / ldmatrix helpers (arch-neutral PTX, sm_80-era: compiles on sm_103)
// ---------------------------------------------------------------------------
__device__ __forceinline__ uint32_t smem_u32(const void* p) {
    uint32_t a;
    asm("{ .reg .u64 t; cvta.to.shared.u64 t, %1; cvt.u32.u64 %0, t; }"
        : "=r"(a) : "l"(p));
    return a;
}
__device__ __forceinline__ void ldsm4(uint32_t& r0, uint32_t& r1, uint32_t& r2,
                                      uint32_t& r3, uint32_t a) {
    asm volatile("ldmatrix.sync.aligned.m8n8.x4.shared.b16 {%0,%1,%2,%3}, [%4];"
                 : "=r"(r0), "=r"(r1), "=r"(r2), "=r"(r3) : "r"(a));
}
__device__ __forceinline__ void ldsm2(uint32_t& r0, uint32_t& r1, uint32_t a) {
    asm volatile("ldmatrix.sync.aligned.m8n8.x2.shared.b16 {%0,%1}, [%2];"
                 : "=r"(r0), "=r"(r1) : "r"(a));
}
__device__ __forceinline__ void mma16816(float* d, uint32_t a0, uint32_t a1,
                                         uint32_t a2, uint32_t a3,
                                         uint32_t b0, uint32_t b1) {
    asm volatile(
        "mma.sync.aligned.m16n8k16.row.col.f32.f16.f16.f32 "
        "{%0,%1,%2,%3}, {%4,%5,%6,%7}, {%8,%9}, {%0,%1,%2,%3};"
        : "+f"(d[0]), "+f"(d[1]), "+f"(d[2]), "+f"(d[3])
        : "r"(a0), "r"(a1), "r"(a2), "r"(a3), "r"(b0), "r"(b1));
}

// ---------------------------------------------------------------------------
// GroupNorm (unchanged — measured cheap)
// ---------------------------------------------------------------------------
__global__ __launch_bounds__(256) void gn_kernel(const float* __restrict__ x,
                                                 const float* __restrict__ sc,
                                                 const float* __restrict__ bi,
                                                 float* __restrict__ h) {
    int b = blockIdx.x >> 5, g = blockIdx.x & 31;
    int tid = threadIdx.x;
    size_t base = ((size_t)b * C_ + (size_t)g * 8) * N_;
    const float4* x4 = (const float4*)(x + base);
    float4* h4 = (float4*)(h + base);

    float s = 0.f, ss = 0.f;
    for (int i = tid; i < 8192; i += 256) {
        float4 v = x4[i];
        s  += v.x + v.y + v.z + v.w;
        ss += v.x * v.x + v.y * v.y + v.z * v.z + v.w * v.w;
    }
    __shared__ float red[512];
    red[tid] = s; red[256 + tid] = ss;
    __syncthreads();
    for (int st = 128; st > 0; st >>= 1) {
        if (tid < st) { red[tid] += red[tid + st]; red[256 + tid] += red[256 + tid + st]; }
        __syncthreads();
    }
    float mean = red[0] * (1.f / 32768.f);
    float var  = red[256] * (1.f / 32768.f) - mean * mean;
    float inv  = rsqrtf(var + 1e-6f);

    for (int i = tid; i < 8192; i += 256) {
        int c = g * 8 + (i >> 10);
        float a  = sc[c] * inv;
        float bb = bi[c] - mean * a;
        float4 v = x4[i];
        h4[i] = make_float4(v.x * a + bb, v.y * a + bb, v.z * a + bb, v.w * a + bb);
    }
}

// ---------------------------------------------------------------------------
// 1x1 conv GEMM. MODE 0: fp32 out [B,C,N] + skip. MODE 1: fp16 out [B,N,C]
// scaled by smul. MODE 2: fp16 out [B,C,N].
// ---------------------------------------------------------------------------
template <int MODE>
__global__ __launch_bounds__(256) void gemm_kernel(const float* __restrict__ A,
                                                   const float* __restrict__ W,
                                                   const float* __restrict__ bias,
                                                   const float* __restrict__ skip,
                                                   void* __restrict__ outv,
                                                   float smul) {
    __shared__ float hs[16][64];
    __shared__ float ws[16][64];
    int b = blockIdx.z;
    int n0 = blockIdx.x * 64, co0 = blockIdx.y * 64;
    int tid = threadIdx.x, tx = tid & 15, ty = tid >> 4;
    const float* Ab = A + (size_t)b * C_ * N_;
    float acc[4][4] = {};

    for (int k0 = 0; k0 < C_; k0 += 16) {
        *(float4*)&hs[ty][tx * 4] =
            *(const float4*)(Ab + (size_t)(k0 + ty) * N_ + n0 + tx * 4);
#pragma unroll
        for (int u = 0; u < 4; u++)
            ws[ty][tx * 4 + u] = W[(size_t)(co0 + tx * 4 + u) * C_ + k0 + ty];
        __syncthreads();
#pragma unroll
        for (int kk = 0; kk < 16; kk++) {
            float4 r4 = (MODE == 1) ? *(float4*)&hs[kk][ty * 4] : *(float4*)&ws[kk][ty * 4];
            float4 c4 = (MODE == 1) ? *(float4*)&ws[kk][tx * 4] : *(float4*)&hs[kk][tx * 4];
            float rv[4] = {r4.x, r4.y, r4.z, r4.w};
            float cv[4] = {c4.x, c4.y, c4.z, c4.w};
#pragma unroll
            for (int a = 0; a < 4; a++)
#pragma unroll
                for (int c = 0; c < 4; c++) acc[a][c] += rv[a] * cv[c];
        }
        __syncthreads();
    }

    if (MODE == 0) {
        float* out = (float*)outv;
#pragma unroll
        for (int a = 0; a < 4; a++) {
            int co = co0 + ty * 4 + a;
            float bb = bias[co];
            size_t off = ((size_t)b * C_ + co) * N_ + n0 + tx * 4;
            float4 r = make_float4(acc[a][0] + bb, acc[a][1] + bb,
                                   acc[a][2] + bb, acc[a][3] + bb);
            float4 s4 = *(const float4*)(skip + off);
            r.x += s4.x; r.y += s4.y; r.z += s4.z; r.w += s4.w;
            *(float4*)(out + off) = r;
        }
    } else if (MODE == 1) {  // fp16 [B,N,C] (rows = tokens), scaled
        __half* out = (__half*)outv;
        float4 b4 = *(const float4*)(bias + co0 + tx * 4);
#pragma unroll
        for (int a = 0; a < 4; a++) {
            int n = n0 + ty * 4 + a;
            size_t off = ((size_t)b * N_ + n) * C_ + co0 + tx * 4;
            __half2 h0 = __floats2half2_rn((acc[a][0] + b4.x) * smul,
                                           (acc[a][1] + b4.y) * smul);
            __half2 h1 = __floats2half2_rn((acc[a][2] + b4.z) * smul,
                                           (acc[a][3] + b4.w) * smul);
            uint2 pk = make_uint2(*(uint32_t*)&h0, *(uint32_t*)&h1);
            *(uint2*)(out + off) = pk;
        }
    } else {  // MODE 2: fp16 [B,C,N] (rows = channels)
        __half* out = (__half*)outv;
#pragma unroll
        for (int a = 0; a < 4; a++) {
            int co = co0 + ty * 4 + a;
            float bb = bias[co];
            size_t off = ((size_t)b * C_ + co) * N_ + n0 + tx * 4;
            __half2 h0 = __floats2half2_rn(acc[a][0] + bb, acc[a][1] + bb);
            __half2 h1 = __floats2half2_rn(acc[a][2] + bb, acc[a][3] + bb);
            uint2 pk = make_uint2(*(uint32_t*)&h0, *(uint32_t*)&h1);
            *(uint2*)(out + off) = pk;
        }
    }
}

// ---------------------------------------------------------------------------
// mma.sync fp16 flash attention, no-max single pass.
// CTA: 128 queries, 8 warps (16 q each), key tile 64. Grid (32, B).
//   qt (pre-scaled by log2e/16), kt: [B,N,C] fp16. vc: [B,C,N] fp16.
// Smem (padded rows for conflict-free ldmatrix):
//   Qs [128][528B], Ks [64][528B], Vs [264][144B] (rows 256-263 = ones -> l).
// Per warp: S frag 8 nb x 4 fp32; P repacked in regs; O accum 33 cb x 4 fp32.
// ---------------------------------------------------------------------------
#define QT 128
#define KT 64
#define QROW 528   // bytes per Q/K smem row (512 + 16 pad)
#define VROW 144   // bytes per V smem row (128 + 16 pad)
#define SM_K (128 * QROW)
#define SM_V (SM_K + 64 * QROW)
#define ATTN_SMEM (SM_V + 264 * VROW)

__global__ __launch_bounds__(256, 1) void attn_mma(const __half* __restrict__ qt,
                                                   const __half* __restrict__ kt,
                                                   const __half* __restrict__ vc,
                                                   float* __restrict__ z) {
    extern __shared__ char smem[];
    uint32_t sb = smem_u32(smem);
    int tid = threadIdx.x, wid = tid >> 5, lane = tid & 31;
    int b = blockIdx.y, q0 = blockIdx.x * QT;
    int qw = wid * 16;
    int g = lane >> 2, t4 = lane & 3;

    // ---- Load Q tile: 128 rows x 512B ----
    {
        const uint4* qg = (const uint4*)(qt + ((size_t)b * N_ + q0) * C_);
#pragma unroll
        for (int it = 0; it < 16; it++) {
            int seg = it * 256 + tid;
            int row = seg >> 5, col = seg & 31;
            *(uint4*)(smem + row * QROW + col * 16) = qg[row * 32 + col];
        }
    }
    // ---- Ones rows of V tile (l accumulator channel block) ----
    {
        __half one = __float2half(1.0f);
        for (int idx = tid; idx < 512; idx += 256) {
            int row = 256 + (idx >> 6), colh = idx & 63;
            *(__half*)(smem + SM_V + row * VROW + colh * 2) = one;
        }
    }

    // ldmatrix base addresses (valid for all 32 lanes)
    int lrow8 = lane & 7, lhalf = (lane >> 3) & 1;
    uint32_t aBase = sb + (qw + lrow8 + lhalf * 8) * QROW + (lane >> 4) * 16;
    uint32_t bBase = sb + SM_K + lrow8 * QROW + lhalf * 16;
    uint32_t vBase = sb + SM_V + lrow8 * VROW + lhalf * 16;

    float O[33][4];
#pragma unroll
    for (int cb = 0; cb < 33; cb++)
#pragma unroll
        for (int e = 0; e < 4; e++) O[cb][e] = 0.f;

    for (int j0 = 0; j0 < N_; j0 += KT) {
        // ---- Load K tile: 64 rows x 512B ----
        const uint4* kg = (const uint4*)(kt + ((size_t)b * N_ + j0) * C_);
#pragma unroll
        for (int it = 0; it < 8; it++) {
            int seg = it * 256 + tid;
            int row = seg >> 5, col = seg & 31;
            *(uint4*)(smem + SM_K + row * QROW + col * 16) = kg[row * 32 + col];
        }
        // ---- Load V tile: 256 rows x 128B ----
#pragma unroll
        for (int it = 0; it < 8; it++) {
            int seg = it * 256 + tid;
            int row = seg >> 3, col = seg & 7;
            *(uint4*)(smem + SM_V + row * VROW + col * 16) =
                *(const uint4*)(vc + ((size_t)b * C_ + row) * N_ + j0 + col * 8);
        }
        __syncthreads();

        // ---- S = Q'^T K (S already in log2 units; q pre-scaled) ----
        float S[8][4];
#pragma unroll
        for (int nb = 0; nb < 8; nb++)
#pragma unroll
            for (int e = 0; e < 4; e++) S[nb][e] = 0.f;

        for (int kk = 0; kk < 16; kk++) {
            uint32_t a0, a1, a2, a3;
            ldsm4(a0, a1, a2, a3, aBase + kk * 32);
#pragma unroll
            for (int nb = 0; nb < 8; nb++) {
                uint32_t b0, b1;
                ldsm2(b0, b1, bBase + nb * 8 * QROW + kk * 32);
                mma16816(S[nb], a0, a1, a2, a3, b0, b1);
            }
        }

        // ---- P = exp2(S) as fp16 mma A-fragments ----
        uint32_t P[16];
#pragma unroll
        for (int nb = 0; nb < 8; nb++) {
            __half2 e0 = h2exp2(__floats2half2_rn(S[nb][0], S[nb][1]));
            __half2 e1 = h2exp2(__floats2half2_rn(S[nb][2], S[nb][3]));
            P[nb * 2]     = *(uint32_t*)&e0;
            P[nb * 2 + 1] = *(uint32_t*)&e1;
        }

        // ---- O += P V^T  (block 32 = ones rows -> row sums l) ----
#pragma unroll
        for (int jj = 0; jj < 4; jj++) {
            uint32_t a0 = P[jj * 4], a1 = P[jj * 4 + 1];
            uint32_t a2 = P[jj * 4 + 2], a3 = P[jj * 4 + 3];
#pragma unroll
            for (int cb = 0; cb < 33; cb++) {
                uint32_t b0, b1;
                ldsm2(b0, b1, vBase + cb * 8 * VROW + jj * 32);
                mma16816(O[cb], a0, a1, a2, a3, b0, b1);
            }
        }
        __syncthreads();
    }

    // ---- Epilogue: divide by l, write z [B,C,N] fp32 ----
    float inv0 = 1.f / O[32][0];  // row g    (all ones-cols identical)
    float inv1 = 1.f / O[32][2];  // row g+8
    float* zb = z + (size_t)b * C_ * N_ + q0 + qw;
#pragma unroll
    for (int cb = 0; cb < 32; cb++) {
        int c = cb * 8 + t4 * 2;
        zb[(size_t)c * N_ + g]           = O[cb][0] * inv0;
        zb[(size_t)(c + 1) * N_ + g]     = O[cb][1] * inv0;
        zb[(size_t)c * N_ + g + 8]       = O[cb][2] * inv1;
        zb[(size_t)(c + 1) * N_ + g + 8] = O[cb][3] * inv1;
    }
}

// ---------------------------------------------------------------------------
extern "C" void kernel_launch(void* const* d_in, const int* in_sizes, int n_in,
                              void* d_out, int out_size) {
    const float* x  = (const float*)d_in[0];
    const float* gs = (const float*)d_in[1];
    const float* gb = (const float*)d_in[2];
    const float* wq = (const float*)d_in[3];
    const float* bq = (const float*)d_in[4];
    const float* wk = (const float*)d_in[5];
    const float* bk = (const float*)d_in[6];
    const float* wv = (const float*)d_in[7];
    const float* bv = (const float*)d_in[8];
    const float* wo = (const float*)d_in[9];
    const float* bo = (const float*)d_in[10];
    float* out = (float*)d_out;

    float *h, *zp;
    __half *qp, *kp, *vp;
    cudaGetSymbolAddress((void**)&h,  g_h);
    cudaGetSymbolAddress((void**)&qp, g_qt);
    cudaGetSymbolAddress((void**)&kp, g_kt);
    cudaGetSymbolAddress((void**)&vp, g_vc);
    cudaGetSymbolAddress((void**)&zp, g_z);

    cudaFuncSetAttribute(attn_mma, cudaFuncAttributeMaxDynamicSharedMemorySize,
                         ATTN_SMEM);

    gn_kernel<<<B_ * 32, 256>>>(x, gs, gb, h);

    const float QSCALE = 1.4426950408889634f / 16.0f;  // log2(e)/sqrt(C)
    dim3 gg(N_ / 64, C_ / 64, B_);
    gemm_kernel<1><<<gg, 256>>>(h, wq, bq, nullptr, qp, QSCALE);  // q fp16 [B,N,C]
    gemm_kernel<1><<<gg, 256>>>(h, wk, bk, nullptr, kp, 1.0f);    // k fp16 [B,N,C]
    gemm_kernel<2><<<gg, 256>>>(h, wv, bv, nullptr, vp, 1.0f);    // v fp16 [B,C,N]

    attn_mma<<<dim3(N_ / QT, B_), 256, ATTN_SMEM>>>(qp, kp, vp, zp);

    gemm_kernel<0><<<gg, 256>>>(zp, wo, bo, x, out, 1.0f);        // + skip, fp32
}

// round 7
// speedup vs baseline: 7.6907x; 1.7952x over previous
#include <cuda_runtime.h>
#include <cuda_fp16.h>
#include <cstdint>

#define B_ 8
#define C_ 256
#define N_ 4096
#define ELEMS (B_ * C_ * N_)

// Scratch (device globals; no allocation anywhere)
__device__ __half g_ht[ELEMS];  // [B,N,C] normalized activations, fp16 token-major
__device__ __half g_qt[ELEMS];  // [B,N,C] fp16 (pre-scaled by log2e/16)
__device__ __half g_kt[ELEMS];  // [B,N,C] fp16
__device__ __half g_vc[ELEMS];  // [B,C,N] fp16 channel-major
__device__ __half g_zt[ELEMS];  // [B,N,C] attention output fp16

// ---------------------------------------------------------------------------
// mma.sync / ldmatrix helpers (arch-neutral PTX; verified on this harness)
// ---------------------------------------------------------------------------
__device__ __forceinline__ uint32_t smem_u32(const void* p) {
    uint32_t a;
    asm("{ .reg .u64 t; cvta.to.shared.u64 t, %1; cvt.u32.u64 %0, t; }"
        : "=r"(a) : "l"(p));
    return a;
}
__device__ __forceinline__ void ldsm4(uint32_t& r0, uint32_t& r1, uint32_t& r2,
                                      uint32_t& r3, uint32_t a) {
    asm volatile("ldmatrix.sync.aligned.m8n8.x4.shared.b16 {%0,%1,%2,%3}, [%4];"
                 : "=r"(r0), "=r"(r1), "=r"(r2), "=r"(r3) : "r"(a));
}
__device__ __forceinline__ void ldsm2(uint32_t& r0, uint32_t& r1, uint32_t a) {
    asm volatile("ldmatrix.sync.aligned.m8n8.x2.shared.b16 {%0,%1}, [%2];"
                 : "=r"(r0), "=r"(r1) : "r"(a));
}
__device__ __forceinline__ void mma16816(float* d, uint32_t a0, uint32_t a1,
                                         uint32_t a2, uint32_t a3,
                                         uint32_t b0, uint32_t b1) {
    asm volatile(
        "mma.sync.aligned.m16n8k16.row.col.f32.f16.f16.f32 "
        "{%0,%1,%2,%3}, {%4,%5,%6,%7}, {%8,%9}, {%0,%1,%2,%3};"
        : "+f"(d[0]), "+f"(d[1]), "+f"(d[2]), "+f"(d[3])
        : "r"(a0), "r"(a1), "r"(a2), "r"(a3), "r"(b0), "r"(b1));
}

// ---------------------------------------------------------------------------
// GroupNorm -> fp16 token-major hT [B,N,C]. One block per (batch, group).
// Pass 1: stats over 8ch x 4096. Pass 2: smem transpose, 16B stores per token.
// ---------------------------------------------------------------------------
__global__ __launch_bounds__(256) void gn_kernel(const float* __restrict__ x,
                                                 const float* __restrict__ sc,
                                                 const float* __restrict__ bi,
                                                 __half* __restrict__ hT) {
    int b = blockIdx.x >> 5, g = blockIdx.x & 31;
    int tid = threadIdx.x;
    size_t base = ((size_t)b * C_ + (size_t)g * 8) * N_;
    const float4* x4 = (const float4*)(x + base);

    float s = 0.f, ss = 0.f;
    for (int i = tid; i < 8192; i += 256) {
        float4 v = x4[i];
        s  += v.x + v.y + v.z + v.w;
        ss += v.x * v.x + v.y * v.y + v.z * v.z + v.w * v.w;
    }
    __shared__ float red[512];
    red[tid] = s; red[256 + tid] = ss;
    __syncthreads();
    for (int st = 128; st > 0; st >>= 1) {
        if (tid < st) { red[tid] += red[tid + st]; red[256 + tid] += red[256 + tid + st]; }
        __syncthreads();
    }
    float mean = red[0] * (1.f / 32768.f);
    float var  = red[256] * (1.f / 32768.f) - mean * mean;
    float inv  = rsqrtf(var + 1e-6f);

    float aa[8], bb[8];
#pragma unroll
    for (int i = 0; i < 8; i++) {
        int c = g * 8 + i;
        aa[i] = sc[c] * inv;
        bb[i] = bi[c] - mean * aa[i];
    }

    __shared__ float tb[8][520];
    __half* hb = hT + (size_t)b * N_ * C_ + g * 8;
    for (int ch = 0; ch < 8; ch++) {
        int nb = ch * 512;
#pragma unroll
        for (int it = 0; it < 4; it++) {
            int seg = it * 256 + tid;
            int row = seg >> 7, col = seg & 127;
            float4 v = x4[(size_t)row * 1024 + (nb >> 2) + col];
            *(float4*)&tb[row][col * 4] = v;
        }
        __syncthreads();
#pragma unroll
        for (int u = 0; u < 2; u++) {
            int nl = tid * 2 + u;
            __half2 h0 = __floats2half2_rn(tb[0][nl] * aa[0] + bb[0],
                                           tb[1][nl] * aa[1] + bb[1]);
            __half2 h1 = __floats2half2_rn(tb[2][nl] * aa[2] + bb[2],
                                           tb[3][nl] * aa[3] + bb[3]);
            __half2 h2 = __floats2half2_rn(tb[4][nl] * aa[4] + bb[4],
                                           tb[5][nl] * aa[5] + bb[5]);
            __half2 h3 = __floats2half2_rn(tb[6][nl] * aa[6] + bb[6],
                                           tb[7][nl] * aa[7] + bb[7]);
            uint4 pk = make_uint4(*(uint32_t*)&h0, *(uint32_t*)&h1,
                                  *(uint32_t*)&h2, *(uint32_t*)&h3);
            *(uint4*)(hb + (size_t)(nb + nl) * C_) = pk;
        }
        __syncthreads();
    }
}

// ---------------------------------------------------------------------------
// Tensor-core 1x1 conv GEMM over hT [B,N,C] and W [O,C] (both k=C contiguous).
// Block: 128-token x 64-outch tile, K=256 in four 64-wide smem panels.
// MODE 0: D=[n][co] -> fp16 [B,N,C], (acc+bias)*smul      (q, k)
// MODE 1: D=[co][n] -> fp16 [B,C,N], acc+bias             (v)
// MODE 2: D=[co][n] -> fp32 [B,C,N], acc+bias+skip        (o, final output)
// Smem pitch 72 halfs = 144B: +16B per row => conflict-free ldmatrix.
// ---------------------------------------------------------------------------
template <int MODE>
__global__ __launch_bounds__(256) void mma_gemm(const __half* __restrict__ hT,
                                                const float* __restrict__ W,
                                                const float* __restrict__ bias,
                                                const float* __restrict__ skip,
                                                void* __restrict__ outv,
                                                float smul) {
    __shared__ __align__(16) __half hPan[128][72];
    __shared__ __align__(16) __half wPan[64][72];
    int b = blockIdx.z;
    int n0 = blockIdx.x * 128, co0 = blockIdx.y * 64;
    int tid = threadIdx.x, wid = tid >> 5, lane = tid & 31;
    int g = lane >> 2, t4 = lane & 3;
    int lrow8 = lane & 7, lhalf = (lane >> 3) & 1;

    uint32_t hB = smem_u32(hPan), wB = smem_u32(wPan);
    uint32_t aBase, bBase;
    if (MODE == 0) {  // A = hT rows (tokens), B = W rows (outch)
        int qw = wid * 16;
        aBase = hB + (qw + lrow8 + lhalf * 8) * 144 + (lane >> 4) * 16;
        bBase = wB + lrow8 * 144 + lhalf * 16;
    } else {          // A = W rows (outch), B = hT rows (tokens)
        int wc = (wid & 3) * 16, wn = (wid >> 2) * 64;
        aBase = wB + (wc + lrow8 + lhalf * 8) * 144 + (lane >> 4) * 16;
        bBase = hB + (wn + lrow8) * 144 + lhalf * 16;
    }

    float D[8][4];
#pragma unroll
    for (int nb = 0; nb < 8; nb++)
#pragma unroll
        for (int e = 0; e < 4; e++) D[nb][e] = 0.f;

    const __half* hG = hT + ((size_t)b * N_ + n0) * C_;
    for (int k0 = 0; k0 < C_; k0 += 64) {
        // hT panel: 128 rows x 64 halfs (8 x uint4 per row)
#pragma unroll
        for (int it = 0; it < 4; it++) {
            int seg = it * 256 + tid;
            int row = seg >> 3, col = seg & 7;
            *(uint4*)&hPan[row][col * 8] =
                *(const uint4*)(hG + (size_t)row * C_ + k0 + col * 8);
        }
        // W panel: 64 rows x 64 floats -> fp16
#pragma unroll
        for (int it = 0; it < 8; it++) {
            int seg = it * 256 + tid;
            int row = seg >> 5, col = seg & 31;
            float2 wv = *(const float2*)(W + (size_t)(co0 + row) * C_ + k0 + col * 2);
            __half2 wh = __floats2half2_rn(wv.x, wv.y);
            *(__half2*)&wPan[row][col * 2] = wh;
        }
        __syncthreads();
#pragma unroll
        for (int kk = 0; kk < 4; kk++) {
            uint32_t a0, a1, a2, a3;
            ldsm4(a0, a1, a2, a3, aBase + kk * 32);
#pragma unroll
            for (int nb = 0; nb < 8; nb++) {
                uint32_t b0, b1;
                ldsm2(b0, b1, bBase + nb * 8 * 144 + kk * 32);
                mma16816(D[nb], a0, a1, a2, a3, b0, b1);
            }
        }
        __syncthreads();
    }

    if (MODE == 0) {
        __half* out = (__half*)outv;
        size_t row0 = (size_t)b * N_ + n0 + wid * 16 + g;
#pragma unroll
        for (int nb = 0; nb < 8; nb++) {
            int co = co0 + nb * 8 + t4 * 2;
            float b0 = bias[co], b1 = bias[co + 1];
            __half2 h0 = __floats2half2_rn((D[nb][0] + b0) * smul, (D[nb][1] + b1) * smul);
            __half2 h1 = __floats2half2_rn((D[nb][2] + b0) * smul, (D[nb][3] + b1) * smul);
            *(__half2*)(out + row0 * C_ + co) = h0;
            *(__half2*)(out + (row0 + 8) * C_ + co) = h1;
        }
    } else if (MODE == 1) {
        __half* out = (__half*)outv;
        int co_r = co0 + (wid & 3) * 16 + g;
        float b0 = bias[co_r], b1 = bias[co_r + 8];
        size_t base0 = ((size_t)b * C_ + co_r) * N_ + n0 + (wid >> 2) * 64;
#pragma unroll
        for (int nb = 0; nb < 8; nb++) {
            int n = nb * 8 + t4 * 2;
            __half2 h0 = __floats2half2_rn(D[nb][0] + b0, D[nb][1] + b0);
            __half2 h1 = __floats2half2_rn(D[nb][2] + b1, D[nb][3] + b1);
            *(__half2*)(out + base0 + n) = h0;
            *(__half2*)(out + base0 + 8 * (size_t)N_ + n) = h1;
        }
    } else {
        float* out = (float*)outv;
        int co_r = co0 + (wid & 3) * 16 + g;
        float b0 = bias[co_r], b1 = bias[co_r + 8];
        size_t base0 = ((size_t)b * C_ + co_r) * N_ + n0 + (wid >> 2) * 64;
#pragma unroll
        for (int nb = 0; nb < 8; nb++) {
            int n = nb * 8 + t4 * 2;
            float2 s0 = *(const float2*)(skip + base0 + n);
            float2 s1 = *(const float2*)(skip + base0 + 8 * (size_t)N_ + n);
            float2 r0 = make_float2(D[nb][0] + b0 + s0.x, D[nb][1] + b0 + s0.y);
            float2 r1 = make_float2(D[nb][2] + b1 + s1.x, D[nb][3] + b1 + s1.y);
            *(float2*)(out + base0 + n) = r0;
            *(float2*)(out + base0 + 8 * (size_t)N_ + n) = r1;
        }
    }
}

// ---------------------------------------------------------------------------
// mma.sync fp16 flash attention, no-max single pass (verified core from R4).
// Epilogue writes zT fp16 [B,N,C] (contiguous half2 stores).
// ---------------------------------------------------------------------------
#define QT 128
#define KT 64
#define QROW 528
#define VROW 144
#define SM_K (128 * QROW)
#define SM_V (SM_K + 64 * QROW)
#define ATTN_SMEM (SM_V + 264 * VROW)

__global__ __launch_bounds__(256, 1) void attn_mma(const __half* __restrict__ qt,
                                                   const __half* __restrict__ kt,
                                                   const __half* __restrict__ vc,
                                                   __half* __restrict__ zT) {
    extern __shared__ char smem[];
    uint32_t sb = smem_u32(smem);
    int tid = threadIdx.x, wid = tid >> 5, lane = tid & 31;
    int b = blockIdx.y, q0 = blockIdx.x * QT;
    int qw = wid * 16;
    int g = lane >> 2, t4 = lane & 3;

    {
        const uint4* qg = (const uint4*)(qt + ((size_t)b * N_ + q0) * C_);
#pragma unroll
        for (int it = 0; it < 16; it++) {
            int seg = it * 256 + tid;
            int row = seg >> 5, col = seg & 31;
            *(uint4*)(smem + row * QROW + col * 16) = qg[row * 32 + col];
        }
    }
    {
        __half one = __float2half(1.0f);
        for (int idx = tid; idx < 512; idx += 256) {
            int row = 256 + (idx >> 6), colh = idx & 63;
            *(__half*)(smem + SM_V + row * VROW + colh * 2) = one;
        }
    }

    int lrow8 = lane & 7, lhalf = (lane >> 3) & 1;
    uint32_t aBase = sb + (qw + lrow8 + lhalf * 8) * QROW + (lane >> 4) * 16;
    uint32_t bBase = sb + SM_K + lrow8 * QROW + lhalf * 16;
    uint32_t vBase = sb + SM_V + lrow8 * VROW + lhalf * 16;

    float O[33][4];
#pragma unroll
    for (int cb = 0; cb < 33; cb++)
#pragma unroll
        for (int e = 0; e < 4; e++) O[cb][e] = 0.f;

    for (int j0 = 0; j0 < N_; j0 += KT) {
        const uint4* kg = (const uint4*)(kt + ((size_t)b * N_ + j0) * C_);
#pragma unroll
        for (int it = 0; it < 8; it++) {
            int seg = it * 256 + tid;
            int row = seg >> 5, col = seg & 31;
            *(uint4*)(smem + SM_K + row * QROW + col * 16) = kg[row * 32 + col];
        }
#pragma unroll
        for (int it = 0; it < 8; it++) {
            int seg = it * 256 + tid;
            int row = seg >> 3, col = seg & 7;
            *(uint4*)(smem + SM_V + row * VROW + col * 16) =
                *(const uint4*)(vc + ((size_t)b * C_ + row) * N_ + j0 + col * 8);
        }
        __syncthreads();

        float S[8][4];
#pragma unroll
        for (int nb = 0; nb < 8; nb++)
#pragma unroll
            for (int e = 0; e < 4; e++) S[nb][e] = 0.f;

        for (int kk = 0; kk < 16; kk++) {
            uint32_t a0, a1, a2, a3;
            ldsm4(a0, a1, a2, a3, aBase + kk * 32);
#pragma unroll
            for (int nb = 0; nb < 8; nb++) {
                uint32_t b0, b1;
                ldsm2(b0, b1, bBase + nb * 8 * QROW + kk * 32);
                mma16816(S[nb], a0, a1, a2, a3, b0, b1);
            }
        }

        uint32_t P[16];
#pragma unroll
        for (int nb = 0; nb < 8; nb++) {
            __half2 e0 = h2exp2(__floats2half2_rn(S[nb][0], S[nb][1]));
            __half2 e1 = h2exp2(__floats2half2_rn(S[nb][2], S[nb][3]));
            P[nb * 2]     = *(uint32_t*)&e0;
            P[nb * 2 + 1] = *(uint32_t*)&e1;
        }

#pragma unroll
        for (int jj = 0; jj < 4; jj++) {
            uint32_t a0 = P[jj * 4], a1 = P[jj * 4 + 1];
            uint32_t a2 = P[jj * 4 + 2], a3 = P[jj * 4 + 3];
#pragma unroll
            for (int cb = 0; cb < 33; cb++) {
                uint32_t b0, b1;
                ldsm2(b0, b1, vBase + cb * 8 * VROW + jj * 32);
                mma16816(O[cb], a0, a1, a2, a3, b0, b1);
            }
        }
        __syncthreads();
    }

    // Epilogue: divide by l (ones-block row sums), write zT fp16 [B,N,C]
    float inv0 = 1.f / O[32][0];
    float inv1 = 1.f / O[32][2];
    __half* zb = zT + ((size_t)b * N_ + q0 + qw) * C_;
#pragma unroll
    for (int cb = 0; cb < 32; cb++) {
        int c = cb * 8 + t4 * 2;
        __half2 h0 = __floats2half2_rn(O[cb][0] * inv0, O[cb][1] * inv0);
        __half2 h1 = __floats2half2_rn(O[cb][2] * inv1, O[cb][3] * inv1);
        *(__half2*)(zb + (size_t)g * C_ + c) = h0;
        *(__half2*)(zb + (size_t)(g + 8) * C_ + c) = h1;
    }
}

// ---------------------------------------------------------------------------
extern "C" void kernel_launch(void* const* d_in, const int* in_sizes, int n_in,
                              void* d_out, int out_size) {
    const float* x  = (const float*)d_in[0];
    const float* gs = (const float*)d_in[1];
    const float* gb = (const float*)d_in[2];
    const float* wq = (const float*)d_in[3];
    const float* bq = (const float*)d_in[4];
    const float* wk = (const float*)d_in[5];
    const float* bk = (const float*)d_in[6];
    const float* wv = (const float*)d_in[7];
    const float* bv = (const float*)d_in[8];
    const float* wo = (const float*)d_in[9];
    const float* bo = (const float*)d_in[10];
    float* out = (float*)d_out;

    __half *hp, *qp, *kp, *vp, *zp;
    cudaGetSymbolAddress((void**)&hp, g_ht);
    cudaGetSymbolAddress((void**)&qp, g_qt);
    cudaGetSymbolAddress((void**)&kp, g_kt);
    cudaGetSymbolAddress((void**)&vp, g_vc);
    cudaGetSymbolAddress((void**)&zp, g_zt);

    cudaFuncSetAttribute(attn_mma, cudaFuncAttributeMaxDynamicSharedMemorySize,
                         ATTN_SMEM);

    gn_kernel<<<B_ * 32, 256>>>(x, gs, gb, hp);

    const float QSCALE = 1.4426950408889634f / 16.0f;  // log2(e)/sqrt(C)
    dim3 gg(N_ / 128, C_ / 64, B_);
    mma_gemm<0><<<gg, 256>>>(hp, wq, bq, nullptr, qp, QSCALE);
    mma_gemm<0><<<gg, 256>>>(hp, wk, bk, nullptr, kp, 1.0f);
    mma_gemm<1><<<gg, 256>>>(hp, wv, bv, nullptr, vp, 1.0f);

    attn_mma<<<dim3(N_ / QT, B_), 256, ATTN_SMEM>>>(qp, kp, vp, zp);

    mma_gemm<2><<<gg, 256>>>(zp, wo, bo, x, out, 1.0f);
}

// round 11
// speedup vs baseline: 8.0753x; 1.0500x over previous
#include <cuda_runtime.h>
#include <cuda_fp16.h>
#include <cstdint>

#define B_ 8
#define C_ 256
#define N_ 4096
#define ELEMS (B_ * C_ * N_)

// Scratch (device globals; no allocation anywhere)
__device__ __half g_ht[ELEMS];  // [B,N,C] normalized activations, fp16 token-major
__device__ __half g_qt[ELEMS];  // [B,N,C] fp16 (pre-scaled by log2e/16)
__device__ __half g_kt[ELEMS];  // [B,N,C] fp16
__device__ __half g_vc[ELEMS];  // [B,C,N] fp16 channel-major
__device__ __half g_zt[ELEMS];  // [B,N,C] attention output fp16

// ---------------------------------------------------------------------------
// mma.sync / ldmatrix / cp.async helpers (arch-neutral PTX)
// ---------------------------------------------------------------------------
__device__ __forceinline__ uint32_t smem_u32(const void* p) {
    uint32_t a;
    asm("{ .reg .u64 t; cvta.to.shared.u64 t, %1; cvt.u32.u64 %0, t; }"
        : "=r"(a) : "l"(p));
    return a;
}
__device__ __forceinline__ void ldsm4(uint32_t& r0, uint32_t& r1, uint32_t& r2,
                                      uint32_t& r3, uint32_t a) {
    asm volatile("ldmatrix.sync.aligned.m8n8.x4.shared.b16 {%0,%1,%2,%3}, [%4];"
                 : "=r"(r0), "=r"(r1), "=r"(r2), "=r"(r3) : "r"(a));
}
__device__ __forceinline__ void ldsm2(uint32_t& r0, uint32_t& r1, uint32_t a) {
    asm volatile("ldmatrix.sync.aligned.m8n8.x2.shared.b16 {%0,%1}, [%2];"
                 : "=r"(r0), "=r"(r1) : "r"(a));
}
__device__ __forceinline__ void mma16816(float* d, uint32_t a0, uint32_t a1,
                                         uint32_t a2, uint32_t a3,
                                         uint32_t b0, uint32_t b1) {
    asm volatile(
        "mma.sync.aligned.m16n8k16.row.col.f32.f16.f16.f32 "
        "{%0,%1,%2,%3}, {%4,%5,%6,%7}, {%8,%9}, {%0,%1,%2,%3};"
        : "+f"(d[0]), "+f"(d[1]), "+f"(d[2]), "+f"(d[3])
        : "r"(a0), "r"(a1), "r"(a2), "r"(a3), "r"(b0), "r"(b1));
}
__device__ __forceinline__ void cp16(uint32_t dst, const void* src) {
    asm volatile("cp.async.cg.shared.global [%0], [%1], 16;"
                 :: "r"(dst), "l"(src));
}
#define CP_COMMIT() asm volatile("cp.async.commit_group;" ::: "memory")
#define CP_WAIT1()  asm volatile("cp.async.wait_group 1;" ::: "memory")
#define CP_WAIT0()  asm volatile("cp.async.wait_group 0;" ::: "memory")

// ---------------------------------------------------------------------------
// GroupNorm -> fp16 token-major hT [B,N,C]. (unchanged, measured cheap)
// ---------------------------------------------------------------------------
__global__ __launch_bounds__(256) void gn_kernel(const float* __restrict__ x,
                                                 const float* __restrict__ sc,
                                                 const float* __restrict__ bi,
                                                 __half* __restrict__ hT) {
    int b = blockIdx.x >> 5, g = blockIdx.x & 31;
    int tid = threadIdx.x;
    size_t base = ((size_t)b * C_ + (size_t)g * 8) * N_;
    const float4* x4 = (const float4*)(x + base);

    float s = 0.f, ss = 0.f;
    for (int i = tid; i < 8192; i += 256) {
        float4 v = x4[i];
        s  += v.x + v.y + v.z + v.w;
        ss += v.x * v.x + v.y * v.y + v.z * v.z + v.w * v.w;
    }
    __shared__ float red[512];
    red[tid] = s; red[256 + tid] = ss;
    __syncthreads();
    for (int st = 128; st > 0; st >>= 1) {
        if (tid < st) { red[tid] += red[tid + st]; red[256 + tid] += red[256 + tid + st]; }
        __syncthreads();
    }
    float mean = red[0] * (1.f / 32768.f);
    float var  = red[256] * (1.f / 32768.f) - mean * mean;
    float inv  = rsqrtf(var + 1e-6f);

    float aa[8], bb[8];
#pragma unroll
    for (int i = 0; i < 8; i++) {
        int c = g * 8 + i;
        aa[i] = sc[c] * inv;
        bb[i] = bi[c] - mean * aa[i];
    }

    __shared__ float tb[8][520];
    __half* hb = hT + (size_t)b * N_ * C_ + g * 8;
    for (int ch = 0; ch < 8; ch++) {
        int nb = ch * 512;
#pragma unroll
        for (int it = 0; it < 4; it++) {
            int seg = it * 256 + tid;
            int row = seg >> 7, col = seg & 127;
            float4 v = x4[(size_t)row * 1024 + (nb >> 2) + col];
            *(float4*)&tb[row][col * 4] = v;
        }
        __syncthreads();
#pragma unroll
        for (int u = 0; u < 2; u++) {
            int nl = tid * 2 + u;
            __half2 h0 = __floats2half2_rn(tb[0][nl] * aa[0] + bb[0],
                                           tb[1][nl] * aa[1] + bb[1]);
            __half2 h1 = __floats2half2_rn(tb[2][nl] * aa[2] + bb[2],
                                           tb[3][nl] * aa[3] + bb[3]);
            __half2 h2 = __floats2half2_rn(tb[4][nl] * aa[4] + bb[4],
                                           tb[5][nl] * aa[5] + bb[5]);
            __half2 h3 = __floats2half2_rn(tb[6][nl] * aa[6] + bb[6],
                                           tb[7][nl] * aa[7] + bb[7]);
            uint4 pk = make_uint4(*(uint32_t*)&h0, *(uint32_t*)&h1,
                                  *(uint32_t*)&h2, *(uint32_t*)&h3);
            *(uint4*)(hb + (size_t)(nb + nl) * C_) = pk;
        }
        __syncthreads();
    }
}

// ---------------------------------------------------------------------------
// Tensor-core 1x1 conv GEMM (unchanged from R7 passing version)
// ---------------------------------------------------------------------------
template <int MODE>
__global__ __launch_bounds__(256) void mma_gemm(const __half* __restrict__ hT,
                                                const float* __restrict__ W,
                                                const float* __restrict__ bias,
                                                const float* __restrict__ skip,
                                                void* __restrict__ outv,
                                                float smul) {
    __shared__ __align__(16) __half hPan[128][72];
    __shared__ __align__(16) __half wPan[64][72];
    int b = blockIdx.z;
    int n0 = blockIdx.x * 128, co0 = blockIdx.y * 64;
    int tid = threadIdx.x, wid = tid >> 5, lane = tid & 31;
    int g = lane >> 2, t4 = lane & 3;
    int lrow8 = lane & 7, lhalf = (lane >> 3) & 1;

    uint32_t hB = smem_u32(hPan), wB = smem_u32(wPan);
    uint32_t aBase, bBase;
    if (MODE == 0) {
        int qw = wid * 16;
        aBase = hB + (qw + lrow8 + lhalf * 8) * 144 + (lane >> 4) * 16;
        bBase = wB + lrow8 * 144 + lhalf * 16;
    } else {
        int wc = (wid & 3) * 16, wn = (wid >> 2) * 64;
        aBase = wB + (wc + lrow8 + lhalf * 8) * 144 + (lane >> 4) * 16;
        bBase = hB + (wn + lrow8) * 144 + lhalf * 16;
    }

    float D[8][4];
#pragma unroll
    for (int nb = 0; nb < 8; nb++)
#pragma unroll
        for (int e = 0; e < 4; e++) D[nb][e] = 0.f;

    const __half* hG = hT + ((size_t)b * N_ + n0) * C_;
    for (int k0 = 0; k0 < C_; k0 += 64) {
#pragma unroll
        for (int it = 0; it < 4; it++) {
            int seg = it * 256 + tid;
            int row = seg >> 3, col = seg & 7;
            *(uint4*)&hPan[row][col * 8] =
                *(const uint4*)(hG + (size_t)row * C_ + k0 + col * 8);
        }
#pragma unroll
        for (int it = 0; it < 8; it++) {
            int seg = it * 256 + tid;
            int row = seg >> 5, col = seg & 31;
            float2 wv = *(const float2*)(W + (size_t)(co0 + row) * C_ + k0 + col * 2);
            __half2 wh = __floats2half2_rn(wv.x, wv.y);
            *(__half2*)&wPan[row][col * 2] = wh;
        }
        __syncthreads();
#pragma unroll
        for (int kk = 0; kk < 4; kk++) {
            uint32_t a0, a1, a2, a3;
            ldsm4(a0, a1, a2, a3, aBase + kk * 32);
#pragma unroll
            for (int nb = 0; nb < 8; nb++) {
                uint32_t b0, b1;
                ldsm2(b0, b1, bBase + nb * 8 * 144 + kk * 32);
                mma16816(D[nb], a0, a1, a2, a3, b0, b1);
            }
        }
        __syncthreads();
    }

    if (MODE == 0) {
        __half* out = (__half*)outv;
        size_t row0 = (size_t)b * N_ + n0 + wid * 16 + g;
#pragma unroll
        for (int nb = 0; nb < 8; nb++) {
            int co = co0 + nb * 8 + t4 * 2;
            float b0 = bias[co], b1 = bias[co + 1];
            __half2 h0 = __floats2half2_rn((D[nb][0] + b0) * smul, (D[nb][1] + b1) * smul);
            __half2 h1 = __floats2half2_rn((D[nb][2] + b0) * smul, (D[nb][3] + b1) * smul);
            *(__half2*)(out + row0 * C_ + co) = h0;
            *(__half2*)(out + (row0 + 8) * C_ + co) = h1;
        }
    } else if (MODE == 1) {
        __half* out = (__half*)outv;
        int co_r = co0 + (wid & 3) * 16 + g;
        float b0 = bias[co_r], b1 = bias[co_r + 8];
        size_t base0 = ((size_t)b * C_ + co_r) * N_ + n0 + (wid >> 2) * 64;
#pragma unroll
        for (int nb = 0; nb < 8; nb++) {
            int n = nb * 8 + t4 * 2;
            __half2 h0 = __floats2half2_rn(D[nb][0] + b0, D[nb][1] + b0);
            __half2 h1 = __floats2half2_rn(D[nb][2] + b1, D[nb][3] + b1);
            *(__half2*)(out + base0 + n) = h0;
            *(__half2*)(out + base0 + 8 * (size_t)N_ + n) = h1;
        }
    } else {
        float* out = (float*)outv;
        int co_r = co0 + (wid & 3) * 16 + g;
        float b0 = bias[co_r], b1 = bias[co_r + 8];
        size_t base0 = ((size_t)b * C_ + co_r) * N_ + n0 + (wid >> 2) * 64;
#pragma unroll
        for (int nb = 0; nb < 8; nb++) {
            int n = nb * 8 + t4 * 2;
            float2 s0 = *(const float2*)(skip + base0 + n);
            float2 s1 = *(const float2*)(skip + base0 + 8 * (size_t)N_ + n);
            float2 r0 = make_float2(D[nb][0] + b0 + s0.x, D[nb][1] + b0 + s0.y);
            float2 r1 = make_float2(D[nb][2] + b1 + s1.x, D[nb][3] + b1 + s1.y);
            *(float2*)(out + base0 + n) = r0;
            *(float2*)(out + base0 + 8 * (size_t)N_ + n) = r1;
        }
    }
}

// ---------------------------------------------------------------------------
// mma.sync fp16 flash attention, no-max single pass.
// R8: x4 B-operand loads, register l-sums (+shfl quad reduce),
//     cp.async double-buffered K/V tiles.
// Smem: Q[128][528] | K0,K1[64][528] | V0,V1[256][144]  = 204 KB, 1 CTA/SM.
// ---------------------------------------------------------------------------
#define QT 128
#define KT 64
#define QROW 528
#define VROW 144
#define SM_K0 (128 * QROW)
#define SM_K1 (SM_K0 + 64 * QROW)
#define SM_V0 (SM_K1 + 64 * QROW)
#define SM_V1 (SM_V0 + 256 * VROW)
#define ATTN_SMEM (SM_V1 + 256 * VROW)

__global__ __launch_bounds__(256, 1) void attn_mma(const __half* __restrict__ qt,
                                                   const __half* __restrict__ kt,
                                                   const __half* __restrict__ vc,
                                                   __half* __restrict__ zT) {
    extern __shared__ char smem[];
    uint32_t sb = smem_u32(smem);
    int tid = threadIdx.x, wid = tid >> 5, lane = tid & 31;
    int b = blockIdx.y, q0 = blockIdx.x * QT;
    int qw = wid * 16;
    int g = lane >> 2, t4 = lane & 3;
    int lrow8 = lane & 7, lhalf = (lane >> 3) & 1;

    // ---- Load Q tile (plain stores; visible after first barrier) ----
    {
        const uint4* qg = (const uint4*)(qt + ((size_t)b * N_ + q0) * C_);
#pragma unroll
        for (int it = 0; it < 16; it++) {
            int seg = it * 256 + tid;
            int row = seg >> 5, col = seg & 31;
            *(uint4*)(smem + row * QROW + col * 16) = qg[row * 32 + col];
        }
    }

    // ldmatrix bases
    uint32_t aBase = sb + (qw + lrow8 + lhalf * 8) * QROW + (lane >> 4) * 16;
    // x4 B bases: lanes 0-7 nb khalf0 / 8-15 nb khalf1 / 16-23 nb+1 kh0 / 24-31 nb+1 kh1
    uint32_t kOff4 = (lane & 7) * QROW + ((lane >> 3) & 1) * 16 + (lane >> 4) * (8 * QROW);
    uint32_t vOff4 = (lane & 7) * VROW + ((lane >> 3) & 1) * 16 + (lane >> 4) * (8 * VROW);

    const char* kgb = (const char*)(kt + (size_t)b * N_ * C_);
    const __half* vgb = vc + (size_t)b * C_ * N_;

    // async tile loaders
    auto issueK = [&](int j0, uint32_t buf) {
        const char* kg = kgb + (size_t)j0 * (C_ * 2);
#pragma unroll
        for (int it = 0; it < 8; it++) {
            int seg = it * 256 + tid;
            int row = seg >> 5, col = seg & 31;
            cp16(sb + buf + row * QROW + col * 16, kg + (size_t)row * 512 + col * 16);
        }
    };
    auto issueV = [&](int j0, uint32_t buf) {
#pragma unroll
        for (int it = 0; it < 8; it++) {
            int seg = it * 256 + tid;
            int row = seg >> 3, col = seg & 7;
            cp16(sb + buf + row * VROW + col * 16,
                 (const char*)(vgb + (size_t)row * N_ + j0) + col * 16);
        }
    };

    float O[32][4];
#pragma unroll
    for (int cb = 0; cb < 32; cb++)
#pragma unroll
        for (int e = 0; e < 4; e++) O[cb][e] = 0.f;
    float l0 = 0.f, l1 = 0.f;

    issueK(0, SM_K0); issueV(0, SM_V0); CP_COMMIT();

    for (int t = 0; t < N_ / KT; t++) {
        int j0 = t * KT;
        if (t < N_ / KT - 1) {
            uint32_t kb = (t & 1) ? SM_K0 : SM_K1;
            uint32_t vb = (t & 1) ? SM_V0 : SM_V1;
            issueK(j0 + KT, kb); issueV(j0 + KT, vb); CP_COMMIT();
            CP_WAIT1();
        } else {
            CP_WAIT0();
        }
        __syncthreads();
        uint32_t kB = sb + ((t & 1) ? SM_K1 : SM_K0) + kOff4;
        uint32_t vB = sb + ((t & 1) ? SM_V1 : SM_V0) + vOff4;

        // ---- S = Q'^T K (log2 units; q pre-scaled) ----
        float S[8][4];
#pragma unroll
        for (int nb = 0; nb < 8; nb++)
#pragma unroll
            for (int e = 0; e < 4; e++) S[nb][e] = 0.f;

        for (int kk = 0; kk < 16; kk++) {
            uint32_t a0, a1, a2, a3;
            ldsm4(a0, a1, a2, a3, aBase + kk * 32);
#pragma unroll
            for (int nbp = 0; nbp < 4; nbp++) {
                uint32_t b0, b1, b2, b3;
                ldsm4(b0, b1, b2, b3, kB + nbp * (16 * QROW) + kk * 32);
                mma16816(S[2 * nbp],     a0, a1, a2, a3, b0, b1);
                mma16816(S[2 * nbp + 1], a0, a1, a2, a3, b2, b3);
            }
        }

        // ---- P = exp2(S) -> fp16 A-fragments; fp32 row-sum accumulation ----
        uint32_t P[16];
#pragma unroll
        for (int nb = 0; nb < 8; nb++) {
            float e0 = exp2f(S[nb][0]), e1 = exp2f(S[nb][1]);
            float e2 = exp2f(S[nb][2]), e3 = exp2f(S[nb][3]);
            l0 += e0 + e1;
            l1 += e2 + e3;
            __half2 p0 = __floats2half2_rn(e0, e1);
            __half2 p1 = __floats2half2_rn(e2, e3);
            P[nb * 2]     = *(uint32_t*)&p0;
            P[nb * 2 + 1] = *(uint32_t*)&p1;
        }

        // ---- O += P V^T ----
#pragma unroll
        for (int jj = 0; jj < 4; jj++) {
            uint32_t a0 = P[jj * 4], a1 = P[jj * 4 + 1];
            uint32_t a2 = P[jj * 4 + 2], a3 = P[jj * 4 + 3];
#pragma unroll
            for (int cbp = 0; cbp < 16; cbp++) {
                uint32_t b0, b1, b2, b3;
                ldsm4(b0, b1, b2, b3, vB + cbp * (16 * VROW) + jj * 32);
                mma16816(O[2 * cbp],     a0, a1, a2, a3, b0, b1);
                mma16816(O[2 * cbp + 1], a0, a1, a2, a3, b2, b3);
            }
        }
        __syncthreads();
    }

    // ---- l: quad reduce (lanes sharing row differ only in bits 0-1) ----
    l0 += __shfl_xor_sync(0xffffffffu, l0, 1);
    l0 += __shfl_xor_sync(0xffffffffu, l0, 2);
    l1 += __shfl_xor_sync(0xffffffffu, l1, 1);
    l1 += __shfl_xor_sync(0xffffffffu, l1, 2);
    float inv0 = 1.f / l0, inv1 = 1.f / l1;

    __half* zb = zT + ((size_t)b * N_ + q0 + qw) * C_;
#pragma unroll
    for (int cb = 0; cb < 32; cb++) {
        int c = cb * 8 + t4 * 2;
        __half2 h0 = __floats2half2_rn(O[cb][0] * inv0, O[cb][1] * inv0);
        __half2 h1 = __floats2half2_rn(O[cb][2] * inv1, O[cb][3] * inv1);
        *(__half2*)(zb + (size_t)g * C_ + c) = h0;
        *(__half2*)(zb + (size_t)(g + 8) * C_ + c) = h1;
    }
}

// ---------------------------------------------------------------------------
extern "C" void kernel_launch(void* const* d_in, const int* in_sizes, int n_in,
                              void* d_out, int out_size) {
    const float* x  = (const float*)d_in[0];
    const float* gs = (const float*)d_in[1];
    const float* gb = (const float*)d_in[2];
    const float* wq = (const float*)d_in[3];
    const float* bq = (const float*)d_in[4];
    const float* wk = (const float*)d_in[5];
    const float* bk = (const float*)d_in[6];
    const float* wv = (const float*)d_in[7];
    const float* bv = (const float*)d_in[8];
    const float* wo = (const float*)d_in[9];
    const float* bo = (const float*)d_in[10];
    float* out = (float*)d_out;

    __half *hp, *qp, *kp, *vp, *zp;
    cudaGetSymbolAddress((void**)&hp, g_ht);
    cudaGetSymbolAddress((void**)&qp, g_qt);
    cudaGetSymbolAddress((void**)&kp, g_kt);
    cudaGetSymbolAddress((void**)&vp, g_vc);
    cudaGetSymbolAddress((void**)&zp, g_zt);

    cudaFuncSetAttribute(attn_mma, cudaFuncAttributeMaxDynamicSharedMemorySize,
                         ATTN_SMEM);

    gn_kernel<<<B_ * 32, 256>>>(x, gs, gb, hp);

    const float QSCALE = 1.4426950408889634f / 16.0f;  // log2(e)/sqrt(C)
    dim3 gg(N_ / 128, C_ / 64, B_);
    mma_gemm<0><<<gg, 256>>>(hp, wq, bq, nullptr, qp, QSCALE);
    mma_gemm<0><<<gg, 256>>>(hp, wk, bk, nullptr, kp, 1.0f);
    mma_gemm<1><<<gg, 256>>>(hp, wv, bv, nullptr, vp, 1.0f);

    attn_mma<<<dim3(N_ / QT, B_), 256, ATTN_SMEM>>>(qp, kp, vp, zp);

    mma_gemm<2><<<gg, 256>>>(zp, wo, bo, x, out, 1.0f);
}

// round 15
// speedup vs baseline: 8.7734x; 1.0864x over previous
#include <cuda_runtime.h>
#include <cuda_fp16.h>
#include <cstdint>

#define B_ 8
#define C_ 256
#define N_ 4096
#define ELEMS (B_ * C_ * N_)

// Scratch (device globals; no allocation anywhere)
__device__ __half g_ht[ELEMS];       // [B,N,C] normalized activations fp16
__device__ __half g_qt[ELEMS];       // [B,N,C] fp16 (pre-scaled by log2e/16)
__device__ __half g_kt[ELEMS];       // [B,N,C] fp16
__device__ __half g_vc[ELEMS];       // [B,C,N] fp16 channel-major
__device__ __half g_zt[ELEMS];       // [B,N,C] attention output fp16
__device__ __half g_wh[4][C_ * C_];  // fp16 copies of wq,wk,wv,wo

// ---------------------------------------------------------------------------
// helpers (arch-neutral PTX; patterns verified on this harness)
// ---------------------------------------------------------------------------
__device__ __forceinline__ uint32_t smem_u32(const void* p) {
    uint32_t a;
    asm("{ .reg .u64 t; cvta.to.shared.u64 t, %1; cvt.u32.u64 %0, t; }"
        : "=r"(a) : "l"(p));
    return a;
}
__device__ __forceinline__ void ldsm4(uint32_t& r0, uint32_t& r1, uint32_t& r2,
                                      uint32_t& r3, uint32_t a) {
    asm volatile("ldmatrix.sync.aligned.m8n8.x4.shared.b16 {%0,%1,%2,%3}, [%4];"
                 : "=r"(r0), "=r"(r1), "=r"(r2), "=r"(r3) : "r"(a));
}
__device__ __forceinline__ void mma16816(float* d, uint32_t a0, uint32_t a1,
                                         uint32_t a2, uint32_t a3,
                                         uint32_t b0, uint32_t b1) {
    asm volatile(
        "mma.sync.aligned.m16n8k16.row.col.f32.f16.f16.f32 "
        "{%0,%1,%2,%3}, {%4,%5,%6,%7}, {%8,%9}, {%0,%1,%2,%3};"
        : "+f"(d[0]), "+f"(d[1]), "+f"(d[2]), "+f"(d[3])
        : "r"(a0), "r"(a1), "r"(a2), "r"(a3), "r"(b0), "r"(b1));
}
__device__ __forceinline__ void cp16(uint32_t dst, const void* src) {
    asm volatile("cp.async.cg.shared.global [%0], [%1], 16;"
                 :: "r"(dst), "l"(src));
}
__device__ __forceinline__ float fex2(float x) {
    float r;
    asm("ex2.approx.ftz.f32 %0, %1;" : "=f"(r) : "f"(x));
    return r;
}
#define CP_COMMIT() asm volatile("cp.async.commit_group;" ::: "memory")
#define CP_WAIT1()  asm volatile("cp.async.wait_group 1;" ::: "memory")
#define CP_WAIT0()  asm volatile("cp.async.wait_group 0;" ::: "memory")

// ---------------------------------------------------------------------------
// Weight fp32 -> fp16 convert (one 256x256 matrix per launch; ~1us each)
// ---------------------------------------------------------------------------
__global__ __launch_bounds__(256) void wcvt_kernel(const float* __restrict__ w,
                                                   __half* __restrict__ out) {
    int idx = (blockIdx.x * 256 + threadIdx.x) * 4;
    float4 v = *(const float4*)(w + idx);
    __half2 h0 = __floats2half2_rn(v.x, v.y);
    __half2 h1 = __floats2half2_rn(v.z, v.w);
    *(uint2*)(out + idx) = make_uint2(*(uint32_t*)&h0, *(uint32_t*)&h1);
}

// ---------------------------------------------------------------------------
// GroupNorm -> fp16 token-major hT [B,N,C]. (unchanged, measured cheap)
// ---------------------------------------------------------------------------
__global__ __launch_bounds__(256) void gn_kernel(const float* __restrict__ x,
                                                 const float* __restrict__ sc,
                                                 const float* __restrict__ bi,
                                                 __half* __restrict__ hT) {
    int b = blockIdx.x >> 5, g = blockIdx.x & 31;
    int tid = threadIdx.x;
    size_t base = ((size_t)b * C_ + (size_t)g * 8) * N_;
    const float4* x4 = (const float4*)(x + base);

    float s = 0.f, ss = 0.f;
    for (int i = tid; i < 8192; i += 256) {
        float4 v = x4[i];
        s  += v.x + v.y + v.z + v.w;
        ss += v.x * v.x + v.y * v.y + v.z * v.z + v.w * v.w;
    }
    __shared__ float red[512];
    red[tid] = s; red[256 + tid] = ss;
    __syncthreads();
    for (int st = 128; st > 0; st >>= 1) {
        if (tid < st) { red[tid] += red[tid + st]; red[256 + tid] += red[256 + tid + st]; }
        __syncthreads();
    }
    float mean = red[0] * (1.f / 32768.f);
    float var  = red[256] * (1.f / 32768.f) - mean * mean;
    float inv  = rsqrtf(var + 1e-6f);

    float aa[8], bb[8];
#pragma unroll
    for (int i = 0; i < 8; i++) {
        int c = g * 8 + i;
        aa[i] = sc[c] * inv;
        bb[i] = bi[c] - mean * aa[i];
    }

    __shared__ float tb[8][520];
    __half* hb = hT + (size_t)b * N_ * C_ + g * 8;
    for (int ch = 0; ch < 8; ch++) {
        int nb = ch * 512;
#pragma unroll
        for (int it = 0; it < 4; it++) {
            int seg = it * 256 + tid;
            int row = seg >> 7, col = seg & 127;
            float4 v = x4[(size_t)row * 1024 + (nb >> 2) + col];
            *(float4*)&tb[row][col * 4] = v;
        }
        __syncthreads();
#pragma unroll
        for (int u = 0; u < 2; u++) {
            int nl = tid * 2 + u;
            __half2 h0 = __floats2half2_rn(tb[0][nl] * aa[0] + bb[0],
                                           tb[1][nl] * aa[1] + bb[1]);
            __half2 h1 = __floats2half2_rn(tb[2][nl] * aa[2] + bb[2],
                                           tb[3][nl] * aa[3] + bb[3]);
            __half2 h2 = __floats2half2_rn(tb[4][nl] * aa[4] + bb[4],
                                           tb[5][nl] * aa[5] + bb[5]);
            __half2 h3 = __floats2half2_rn(tb[6][nl] * aa[6] + bb[6],
                                           tb[7][nl] * aa[7] + bb[7]);
            uint4 pk = make_uint4(*(uint32_t*)&h0, *(uint32_t*)&h1,
                                  *(uint32_t*)&h2, *(uint32_t*)&h3);
            *(uint4*)(hb + (size_t)(nb + nl) * C_) = pk;
        }
        __syncthreads();
    }
}

// ---------------------------------------------------------------------------
// Tensor-core 1x1 conv GEMM, R12: fp16 weights, cp.async 2-stage panels,
// x4 B-operand loads (pattern verified in attn kernel R11).
// Dynamic smem: hPan 2x128x72, wPan 2x64x72 = 55296 B.
// MODE 0: D=[n][co] -> fp16 [B,N,C], (acc+bias)*smul      (q, k)
// MODE 1: D=[co][n] -> fp16 [B,C,N], acc+bias             (v)
// MODE 2: D=[co][n] -> fp32 [B,C,N], acc+bias+skip        (o, final output)
// ---------------------------------------------------------------------------
#define GP_H (128 * 72 * 2)          // 18432 per h stage
#define GP_W (64 * 72 * 2)           // 9216 per w stage
#define GEMM_SMEM (2 * GP_H + 2 * GP_W)

template <int MODE>
__global__ __launch_bounds__(256) void mma_gemm(const __half* __restrict__ hT,
                                                const __half* __restrict__ W,
                                                const float* __restrict__ bias,
                                                const float* __restrict__ skip,
                                                void* __restrict__ outv,
                                                float smul) {
    extern __shared__ char smg[];
    uint32_t sb = smem_u32(smg);
    int b = blockIdx.z;
    int n0 = blockIdx.x * 128, co0 = blockIdx.y * 64;
    int tid = threadIdx.x, wid = tid >> 5, lane = tid & 31;
    int g = lane >> 2, t4 = lane & 3;
    int lrow8 = lane & 7, lhalf = (lane >> 3) & 1;

    uint32_t aOff, bOff;
    if (MODE == 0) {  // A = hT tokens, B = W outch
        aOff = (wid * 16 + lrow8 + lhalf * 8) * 144 + (lane >> 4) * 16;
        bOff = lrow8 * 144 + lhalf * 16 + (lane >> 4) * (8 * 144);
    } else {          // A = W outch, B = hT tokens
        aOff = ((wid & 3) * 16 + lrow8 + lhalf * 8) * 144 + (lane >> 4) * 16;
        bOff = ((wid >> 2) * 64 + lrow8) * 144 + lhalf * 16 + (lane >> 4) * (8 * 144);
    }

    const __half* hG = hT + ((size_t)b * N_ + n0) * C_;
    auto issue = [&](int k0, int st) {
        uint32_t hD = sb + st * GP_H;
        uint32_t wD = sb + 2 * GP_H + st * GP_W;
#pragma unroll
        for (int it = 0; it < 4; it++) {  // h panel: 128 rows x 128B
            int seg = it * 256 + tid;
            int row = seg >> 3, ck = seg & 7;
            cp16(hD + row * 144 + ck * 16,
                 (const char*)(hG + (size_t)row * C_ + k0) + ck * 16);
        }
#pragma unroll
        for (int it = 0; it < 2; it++) {  // w panel: 64 rows x 128B
            int seg = it * 256 + tid;
            int row = seg >> 3, ck = seg & 7;
            cp16(wD + row * 144 + ck * 16,
                 (const char*)(W + (size_t)(co0 + row) * C_ + k0) + ck * 16);
        }
    };

    float D[8][4];
#pragma unroll
    for (int nb = 0; nb < 8; nb++)
#pragma unroll
        for (int e = 0; e < 4; e++) D[nb][e] = 0.f;

    issue(0, 0); CP_COMMIT();
    for (int ki = 0; ki < 4; ki++) {
        int st = ki & 1;
        if (ki < 3) { issue((ki + 1) * 64, st ^ 1); CP_COMMIT(); CP_WAIT1(); }
        else        { CP_WAIT0(); }
        __syncthreads();
        uint32_t hBase = sb + st * GP_H;
        uint32_t wBase = sb + 2 * GP_H + st * GP_W;
        uint32_t aB = (MODE == 0 ? hBase : wBase) + aOff;
        uint32_t bB = (MODE == 0 ? wBase : hBase) + bOff;
#pragma unroll
        for (int kk = 0; kk < 4; kk++) {
            uint32_t a0, a1, a2, a3;
            ldsm4(a0, a1, a2, a3, aB + kk * 32);
#pragma unroll
            for (int nbp = 0; nbp < 4; nbp++) {
                uint32_t b0, b1, b2, b3;
                ldsm4(b0, b1, b2, b3, bB + nbp * (16 * 144) + kk * 32);
                mma16816(D[2 * nbp],     a0, a1, a2, a3, b0, b1);
                mma16816(D[2 * nbp + 1], a0, a1, a2, a3, b2, b3);
            }
        }
        __syncthreads();
    }

    if (MODE == 0) {
        __half* out = (__half*)outv;
        size_t row0 = (size_t)b * N_ + n0 + wid * 16 + g;
#pragma unroll
        for (int nb = 0; nb < 8; nb++) {
            int co = co0 + nb * 8 + t4 * 2;
            float b0 = bias[co], b1 = bias[co + 1];
            __half2 h0 = __floats2half2_rn((D[nb][0] + b0) * smul, (D[nb][1] + b1) * smul);
            __half2 h1 = __floats2half2_rn((D[nb][2] + b0) * smul, (D[nb][3] + b1) * smul);
            *(__half2*)(out + row0 * C_ + co) = h0;
            *(__half2*)(out + (row0 + 8) * C_ + co) = h1;
        }
    } else if (MODE == 1) {
        __half* out = (__half*)outv;
        int co_r = co0 + (wid & 3) * 16 + g;
        float b0 = bias[co_r], b1 = bias[co_r + 8];
        size_t base0 = ((size_t)b * C_ + co_r) * N_ + n0 + (wid >> 2) * 64;
#pragma unroll
        for (int nb = 0; nb < 8; nb++) {
            int n = nb * 8 + t4 * 2;
            __half2 h0 = __floats2half2_rn(D[nb][0] + b0, D[nb][1] + b0);
            __half2 h1 = __floats2half2_rn(D[nb][2] + b1, D[nb][3] + b1);
            *(__half2*)(out + base0 + n) = h0;
            *(__half2*)(out + base0 + 8 * (size_t)N_ + n) = h1;
        }
    } else {
        float* out = (float*)outv;
        int co_r = co0 + (wid & 3) * 16 + g;
        float b0 = bias[co_r], b1 = bias[co_r + 8];
        size_t base0 = ((size_t)b * C_ + co_r) * N_ + n0 + (wid >> 2) * 64;
#pragma unroll
        for (int nb = 0; nb < 8; nb++) {
            int n = nb * 8 + t4 * 2;
            float2 s0 = *(const float2*)(skip + base0 + n);
            float2 s1 = *(const float2*)(skip + base0 + 8 * (size_t)N_ + n);
            float2 r0 = make_float2(D[nb][0] + b0 + s0.x, D[nb][1] + b0 + s0.y);
            float2 r1 = make_float2(D[nb][2] + b1 + s1.x, D[nb][3] + b1 + s1.y);
            *(float2*)(out + base0 + n) = r0;
            *(float2*)(out + base0 + 8 * (size_t)N_ + n) = r1;
        }
    }
}

// ---------------------------------------------------------------------------
// mma.sync fp16 flash attention (R11-verified core).
// R12 delta: exp2f -> ex2.approx.ftz.f32 (single MUFU op).
// ---------------------------------------------------------------------------
#define QT 128
#define KT 64
#define QROW 528
#define VROW 144
#define SM_K0 (128 * QROW)
#define SM_K1 (SM_K0 + 64 * QROW)
#define SM_V0 (SM_K1 + 64 * QROW)
#define SM_V1 (SM_V0 + 256 * VROW)
#define ATTN_SMEM (SM_V1 + 256 * VROW)

__global__ __launch_bounds__(256, 1) void attn_mma(const __half* __restrict__ qt,
                                                   const __half* __restrict__ kt,
                                                   const __half* __restrict__ vc,
                                                   __half* __restrict__ zT) {
    extern __shared__ char smem[];
    uint32_t sb = smem_u32(smem);
    int tid = threadIdx.x, wid = tid >> 5, lane = tid & 31;
    int b = blockIdx.y, q0 = blockIdx.x * QT;
    int qw = wid * 16;
    int g = lane >> 2, t4 = lane & 3;
    int lrow8 = lane & 7, lhalf = (lane >> 3) & 1;

    {
        const uint4* qg = (const uint4*)(qt + ((size_t)b * N_ + q0) * C_);
#pragma unroll
        for (int it = 0; it < 16; it++) {
            int seg = it * 256 + tid;
            int row = seg >> 5, col = seg & 31;
            *(uint4*)(smem + row * QROW + col * 16) = qg[row * 32 + col];
        }
    }

    uint32_t aBase = sb + (qw + lrow8 + lhalf * 8) * QROW + (lane >> 4) * 16;
    uint32_t kOff4 = (lane & 7) * QROW + ((lane >> 3) & 1) * 16 + (lane >> 4) * (8 * QROW);
    uint32_t vOff4 = (lane & 7) * VROW + ((lane >> 3) & 1) * 16 + (lane >> 4) * (8 * VROW);

    const char* kgb = (const char*)(kt + (size_t)b * N_ * C_);
    const __half* vgb = vc + (size_t)b * C_ * N_;

    auto issueK = [&](int j0, uint32_t buf) {
        const char* kg = kgb + (size_t)j0 * (C_ * 2);
#pragma unroll
        for (int it = 0; it < 8; it++) {
            int seg = it * 256 + tid;
            int row = seg >> 5, col = seg & 31;
            cp16(sb + buf + row * QROW + col * 16, kg + (size_t)row * 512 + col * 16);
        }
    };
    auto issueV = [&](int j0, uint32_t buf) {
#pragma unroll
        for (int it = 0; it < 8; it++) {
            int seg = it * 256 + tid;
            int row = seg >> 3, col = seg & 7;
            cp16(sb + buf + row * VROW + col * 16,
                 (const char*)(vgb + (size_t)row * N_ + j0) + col * 16);
        }
    };

    float O[32][4];
#pragma unroll
    for (int cb = 0; cb < 32; cb++)
#pragma unroll
        for (int e = 0; e < 4; e++) O[cb][e] = 0.f;
    float l0 = 0.f, l1 = 0.f;

    issueK(0, SM_K0); issueV(0, SM_V0); CP_COMMIT();

    for (int t = 0; t < N_ / KT; t++) {
        int j0 = t * KT;
        if (t < N_ / KT - 1) {
            uint32_t kb = (t & 1) ? SM_K0 : SM_K1;
            uint32_t vb = (t & 1) ? SM_V0 : SM_V1;
            issueK(j0 + KT, kb); issueV(j0 + KT, vb); CP_COMMIT();
            CP_WAIT1();
        } else {
            CP_WAIT0();
        }
        __syncthreads();
        uint32_t kB = sb + ((t & 1) ? SM_K1 : SM_K0) + kOff4;
        uint32_t vB = sb + ((t & 1) ? SM_V1 : SM_V0) + vOff4;

        // ---- S = Q'^T K (log2 units; q pre-scaled) ----
        float S[8][4];
#pragma unroll
        for (int nb = 0; nb < 8; nb++)
#pragma unroll
            for (int e = 0; e < 4; e++) S[nb][e] = 0.f;

        for (int kk = 0; kk < 16; kk++) {
            uint32_t a0, a1, a2, a3;
            ldsm4(a0, a1, a2, a3, aBase + kk * 32);
#pragma unroll
            for (int nbp = 0; nbp < 4; nbp++) {
                uint32_t b0, b1, b2, b3;
                ldsm4(b0, b1, b2, b3, kB + nbp * (16 * QROW) + kk * 32);
                mma16816(S[2 * nbp],     a0, a1, a2, a3, b0, b1);
                mma16816(S[2 * nbp + 1], a0, a1, a2, a3, b2, b3);
            }
        }

        // ---- P = exp2(S) via single-MUFU ex2.approx; fp32 row sums ----
        uint32_t P[16];
#pragma unroll
        for (int nb = 0; nb < 8; nb++) {
            float e0 = fex2(S[nb][0]), e1 = fex2(S[nb][1]);
            float e2 = fex2(S[nb][2]), e3 = fex2(S[nb][3]);
            l0 += e0 + e1;
            l1 += e2 + e3;
            __half2 p0 = __floats2half2_rn(e0, e1);
            __half2 p1 = __floats2half2_rn(e2, e3);
            P[nb * 2]     = *(uint32_t*)&p0;
            P[nb * 2 + 1] = *(uint32_t*)&p1;
        }

        // ---- O += P V^T ----
#pragma unroll
        for (int jj = 0; jj < 4; jj++) {
            uint32_t a0 = P[jj * 4], a1 = P[jj * 4 + 1];
            uint32_t a2 = P[jj * 4 + 2], a3 = P[jj * 4 + 3];
#pragma unroll
            for (int cbp = 0; cbp < 16; cbp++) {
                uint32_t b0, b1, b2, b3;
                ldsm4(b0, b1, b2, b3, vB + cbp * (16 * VROW) + jj * 32);
                mma16816(O[2 * cbp],     a0, a1, a2, a3, b0, b1);
                mma16816(O[2 * cbp + 1], a0, a1, a2, a3, b2, b3);
            }
        }
        __syncthreads();
    }

    // ---- l: quad reduce ----
    l0 += __shfl_xor_sync(0xffffffffu, l0, 1);
    l0 += __shfl_xor_sync(0xffffffffu, l0, 2);
    l1 += __shfl_xor_sync(0xffffffffu, l1, 1);
    l1 += __shfl_xor_sync(0xffffffffu, l1, 2);
    float inv0 = 1.f / l0, inv1 = 1.f / l1;

    __half* zb = zT + ((size_t)b * N_ + q0 + qw) * C_;
#pragma unroll
    for (int cb = 0; cb < 32; cb++) {
        int c = cb * 8 + t4 * 2;
        __half2 h0 = __floats2half2_rn(O[cb][0] * inv0, O[cb][1] * inv0);
        __half2 h1 = __floats2half2_rn(O[cb][2] * inv1, O[cb][3] * inv1);
        *(__half2*)(zb + (size_t)g * C_ + c) = h0;
        *(__half2*)(zb + (size_t)(g + 8) * C_ + c) = h1;
    }
}

// ---------------------------------------------------------------------------
extern "C" void kernel_launch(void* const* d_in, const int* in_sizes, int n_in,
                              void* d_out, int out_size) {
    const float* x  = (const float*)d_in[0];
    const float* gs = (const float*)d_in[1];
    const float* gb = (const float*)d_in[2];
    const float* wq = (const float*)d_in[3];
    const float* bq = (const float*)d_in[4];
    const float* wk = (const float*)d_in[5];
    const float* bk = (const float*)d_in[6];
    const float* wv = (const float*)d_in[7];
    const float* bv = (const float*)d_in[8];
    const float* wo = (const float*)d_in[9];
    const float* bo = (const float*)d_in[10];
    float* out = (float*)d_out;

    __half *hp, *qp, *kp, *vp, *zp, *wh;
    cudaGetSymbolAddress((void**)&hp, g_ht);
    cudaGetSymbolAddress((void**)&qp, g_qt);
    cudaGetSymbolAddress((void**)&kp, g_kt);
    cudaGetSymbolAddress((void**)&vp, g_vc);
    cudaGetSymbolAddress((void**)&zp, g_zt);
    cudaGetSymbolAddress((void**)&wh, g_wh);

    cudaFuncSetAttribute(attn_mma, cudaFuncAttributeMaxDynamicSharedMemorySize,
                         ATTN_SMEM);
    cudaFuncSetAttribute(mma_gemm<0>, cudaFuncAttributeMaxDynamicSharedMemorySize,
                         GEMM_SMEM);
    cudaFuncSetAttribute(mma_gemm<1>, cudaFuncAttributeMaxDynamicSharedMemorySize,
                         GEMM_SMEM);
    cudaFuncSetAttribute(mma_gemm<2>, cudaFuncAttributeMaxDynamicSharedMemorySize,
                         GEMM_SMEM);

    // weights -> fp16 (64 blocks x 256 thr x 4 elems = 65536 per matrix)
    wcvt_kernel<<<64, 256>>>(wq, wh);
    wcvt_kernel<<<64, 256>>>(wk, wh + C_ * C_);
    wcvt_kernel<<<64, 256>>>(wv, wh + 2 * C_ * C_);
    wcvt_kernel<<<64, 256>>>(wo, wh + 3 * C_ * C_);

    gn_kernel<<<B_ * 32, 256>>>(x, gs, gb, hp);

    const float QSCALE = 1.4426950408889634f / 16.0f;  // log2(e)/sqrt(C)
    dim3 gg(N_ / 128, C_ / 64, B_);
    mma_gemm<0><<<gg, 256, GEMM_SMEM>>>(hp, wh,              bq, nullptr, qp, QSCALE);
    mma_gemm<0><<<gg, 256, GEMM_SMEM>>>(hp, wh + C_ * C_,    bk, nullptr, kp, 1.0f);
    mma_gemm<1><<<gg, 256, GEMM_SMEM>>>(hp, wh + 2 * C_ * C_, bv, nullptr, vp, 1.0f);

    attn_mma<<<dim3(N_ / QT, B_), 256, ATTN_SMEM>>>(qp, kp, vp, zp);

    mma_gemm<2><<<gg, 256, GEMM_SMEM>>>(zp, wh + 3 * C_ * C_, bo, x, out, 1.0f);
}